// round 13
// baseline (speedup 1.0000x reference)
#include <cuda_runtime.h>
#include <cstdint>

// out[b,f] = -( sum_w x[b,w,f] * W[f,w] + bias[f] )
// x: [512, 5, 25000] f32   W: [25000, 5] f32   bias: [25000] f32   out: [512, 25000] f32
//
// R13 = R6 verbatim (the only kernel that benched 44.8us). A/B vs R12:
// identical except W/bias loads issue BEFORE the 10-x-load burst.
// x-first (R7/R10/R11/R12) benched 47.6-47.9 four times; W-first (R6)
// benched 44.8 once. This re-bench decides whether that was ordering or noise.
//
// Shape: grid 25x256, 256 thr, 4 CTAs/SM, B_PER=2, 10 independent LDG.128
// (.cs) on x, W/bias in conflict-free per-thread SMEM columns, 2 STG.128 (.cs).

#define F_DIM    25000
#define WS       5
#define B_DIM    512
#define B_PER    2
#define NTHREADS 256
#define F4_DIM   (F_DIM / 4)   // 6250

__global__ __launch_bounds__(NTHREADS, 4)
void ocsvm_kernel(const float* __restrict__ x,
                  const float* __restrict__ W,
                  const float* __restrict__ bias,
                  float* __restrict__ out) {
    // w_s[p][tid] holds W[(f + p/5)*5 + p%5]; 4B stride across threads ->
    // bank = tid%32: conflict-free.
    __shared__ float w_s[4 * WS][NTHREADS];

    const int tid = threadIdx.x;
    const int f4  = blockIdx.x * NTHREADS + tid;
    if (f4 >= F4_DIM) return;   // each thread only touches its own smem column
    const int f = f4 * 4;

    // This thread's 20 W floats are contiguous: W[f*5 .. f*5+20) = 5 x float4.
    {
        const float4* W4 = reinterpret_cast<const float4*>(W) + (size_t)f4 * WS;
#pragma unroll
        for (int k = 0; k < WS; k++) {
            float4 q = __ldg(W4 + k);
            w_s[4 * k + 0][tid] = q.x;
            w_s[4 * k + 1][tid] = q.y;
            w_s[4 * k + 2][tid] = q.z;
            w_s[4 * k + 3][tid] = q.w;
        }
    }
    const float4 bb = __ldg(reinterpret_cast<const float4*>(bias + f));
    const float nb0 = -bb.x, nb1 = -bb.y, nb2 = -bb.z, nb3 = -bb.w;

    const int b0 = blockIdx.y * B_PER;

    // Issue ALL 10 streaming loads (both rows) before any math: MLP = 10.
    float4 xv[B_PER][WS];
#pragma unroll
    for (int bi = 0; bi < B_PER; bi++) {
        const size_t base = (size_t)(b0 + bi) * (WS * F_DIM) + f;
#pragma unroll
        for (int wi = 0; wi < WS; wi++) {
            xv[bi][wi] = __ldcs(reinterpret_cast<const float4*>(x + base + (size_t)wi * F_DIM));
        }
    }

#pragma unroll
    for (int bi = 0; bi < B_PER; bi++) {
        float a0 = nb0, a1 = nb1, a2 = nb2, a3 = nb3;
#pragma unroll
        for (int wi = 0; wi < WS; wi++) {
            a0 = fmaf(-xv[bi][wi].x, w_s[0 * WS + wi][tid], a0);
            a1 = fmaf(-xv[bi][wi].y, w_s[1 * WS + wi][tid], a1);
            a2 = fmaf(-xv[bi][wi].z, w_s[2 * WS + wi][tid], a2);
            a3 = fmaf(-xv[bi][wi].w, w_s[3 * WS + wi][tid], a3);
        }
        float4 o; o.x = a0; o.y = a1; o.z = a2; o.w = a3;
        __stcs(reinterpret_cast<float4*>(out + (size_t)(b0 + bi) * F_DIM + f), o);
    }
}

extern "C" void kernel_launch(void* const* d_in, const int* in_sizes, int n_in,
                              void* d_out, int out_size) {
    const float* x    = (const float*)d_in[0];
    const float* W    = (const float*)d_in[1];
    const float* bias = (const float*)d_in[2];
    float* out        = (float*)d_out;

    dim3 grid((F4_DIM + NTHREADS - 1) / NTHREADS,   // 25
              B_DIM / B_PER);                        // 256
    ocsvm_kernel<<<grid, NTHREADS>>>(x, W, bias, out);
}

// round 14
// speedup vs baseline: 1.0007x; 1.0007x over previous
#include <cuda_runtime.h>
#include <cstdint>

// out[b,f] = -( sum_w x[b,w,f] * W[f,w] + bias[f] )
// x: [512, 5, 25000] f32   W: [25000, 5] f32   bias: [25000] f32   out: [512, 25000] f32
//
// FINAL (R14 = R12): fastest kernel measured this session.
//   ncu kernel-time 43.87us, DRAM 81.9% of peak, HBM 6482 GB/s.
// Session evidence: bench wall-time plateaus at 47.6-47.9 for ALL variants
// (R6's lone 44.8 bench did not reproduce); ncu kernel-time discriminates
// and favors this shape.
//
// Shape: grid 25x256, 256 thr, 4 CTAs/SM, B_PER=2 batch rows per block.
// Per block: 10 independent LDG.128 (.cs) on x issued FIRST (160 B in flight
// per thread -> ~160 KB/SM), W/bias loads land behind them into conflict-free
// per-thread SMEM columns (bank = tid%32, no syncs), FMA, 2 STG.128 (.cs).

#define F_DIM    25000
#define WS       5
#define B_DIM    512
#define B_PER    2
#define NTHREADS 256
#define F4_DIM   (F_DIM / 4)   // 6250

__global__ __launch_bounds__(NTHREADS, 4)
void ocsvm_kernel(const float* __restrict__ x,
                  const float* __restrict__ W,
                  const float* __restrict__ bias,
                  float* __restrict__ out) {
    // w_s[p][tid] holds W[(f + p/5)*5 + p%5]; w_s[20..23][tid] = -bias.
    // 4B stride across threads -> bank = tid%32: conflict-free; each thread
    // touches only its own column, so no sync is needed.
    __shared__ float w_s[4 * WS + 4][NTHREADS];

    const int tid = threadIdx.x;
    const int f4  = blockIdx.x * NTHREADS + tid;
    if (f4 >= F4_DIM) return;
    const int f = f4 * 4;

    const int b0 = blockIdx.y * B_PER;

    // ---- Dominant x stream first: 10 independent LDG.128 in flight. ----
    float4 xv[B_PER][WS];
#pragma unroll
    for (int bi = 0; bi < B_PER; bi++) {
        const size_t base = (size_t)(b0 + bi) * (WS * F_DIM) + f;
#pragma unroll
        for (int wi = 0; wi < WS; wi++) {
            xv[bi][wi] = __ldcs(reinterpret_cast<const float4*>(x + base + (size_t)wi * F_DIM));
        }
    }

    // ---- W/bias load lands while x is in flight. ----
    {
        const float4* W4 = reinterpret_cast<const float4*>(W) + (size_t)f4 * WS;
#pragma unroll
        for (int k = 0; k < WS; k++) {
            float4 q = __ldg(W4 + k);
            w_s[4 * k + 0][tid] = q.x;
            w_s[4 * k + 1][tid] = q.y;
            w_s[4 * k + 2][tid] = q.z;
            w_s[4 * k + 3][tid] = q.w;
        }
        const float4 bb = __ldg(reinterpret_cast<const float4*>(bias + f));
        w_s[20][tid] = -bb.x;
        w_s[21][tid] = -bb.y;
        w_s[22][tid] = -bb.z;
        w_s[23][tid] = -bb.w;
    }

#pragma unroll
    for (int bi = 0; bi < B_PER; bi++) {
        float a0 = w_s[20][tid], a1 = w_s[21][tid];
        float a2 = w_s[22][tid], a3 = w_s[23][tid];
#pragma unroll
        for (int wi = 0; wi < WS; wi++) {
            a0 = fmaf(-xv[bi][wi].x, w_s[0 * WS + wi][tid], a0);
            a1 = fmaf(-xv[bi][wi].y, w_s[1 * WS + wi][tid], a1);
            a2 = fmaf(-xv[bi][wi].z, w_s[2 * WS + wi][tid], a2);
            a3 = fmaf(-xv[bi][wi].w, w_s[3 * WS + wi][tid], a3);
        }
        float4 o; o.x = a0; o.y = a1; o.z = a2; o.w = a3;
        __stcs(reinterpret_cast<float4*>(out + (size_t)(b0 + bi) * F_DIM + f), o);
    }
}

extern "C" void kernel_launch(void* const* d_in, const int* in_sizes, int n_in,
                              void* d_out, int out_size) {
    const float* x    = (const float*)d_in[0];
    const float* W    = (const float*)d_in[1];
    const float* bias = (const float*)d_in[2];
    float* out        = (float*)d_out;

    dim3 grid((F4_DIM + NTHREADS - 1) / NTHREADS,   // 25
              B_DIM / B_PER);                        // 256
    ocsvm_kernel<<<grid, NTHREADS>>>(x, W, bias, out);
}